// round 1
// baseline (speedup 1.0000x reference)
#include <cuda_runtime.h>
#include <math.h>

#define D_MODEL 1024
#define D_FF    4096
#define BATCH   2
#define SEQ     2048
#define NHEAD   16
#define HDIM    64
#define BS      (BATCH*SEQ)   // 4096 rows

// ---------------- scratch (device globals; no allocations allowed) ----------
__device__ float g_xn [BS*D_MODEL];
__device__ float g_q  [BS*D_MODEL];
__device__ float g_k  [BS*D_MODEL];
__device__ float g_v  [BS*D_MODEL];
__device__ float g_o  [BS*D_MODEL];
__device__ float g_x1 [BS*D_MODEL];
__device__ float g_xn2[BS*D_MODEL];
__device__ float g_g  [BS*D_FF];
__device__ float g_u  [BS*D_FF];

// ---------------- RMSNorm: one block per row ---------------------------------
__global__ __launch_bounds__(256) void rmsnorm_kernel(const float* __restrict__ x,
        const float* __restrict__ w, float* __restrict__ out)
{
    const int row = blockIdx.x;
    const int t   = threadIdx.x;
    const float4 v = *(const float4*)(x + row*D_MODEL + t*4);
    float ss = v.x*v.x + v.y*v.y + v.z*v.z + v.w*v.w;
    #pragma unroll
    for (int off = 16; off; off >>= 1) ss += __shfl_xor_sync(0xffffffffu, ss, off);
    __shared__ float red[8];
    if ((t & 31) == 0) red[t >> 5] = ss;
    __syncthreads();
    float tot = red[0]+red[1]+red[2]+red[3]+red[4]+red[5]+red[6]+red[7];
    float inv = rsqrtf(tot * (1.0f/D_MODEL) + 1e-5f);
    const float4 wv = *(const float4*)(w + t*4);
    float4 o;
    o.x = v.x*inv*wv.x; o.y = v.y*inv*wv.y; o.z = v.z*inv*wv.z; o.w = v.w*inv*wv.w;
    *(float4*)(out + row*D_MODEL + t*4) = o;
}

// ---------------- SGEMM NT: C[M,N] = A[M,K] * B[N,K]^T (+ optional residual) -
// 128x128 block tile, BK=16, 256 threads, 8x8 microtile, global prefetch.
__global__ __launch_bounds__(256) void sgemm_nt(const float* __restrict__ A,
        const float* __restrict__ B, const float* __restrict__ R,
        float* __restrict__ C, int M, int N, int K)
{
    __shared__ float As[16][128];
    __shared__ float Bs[16][128];
    const int t  = threadIdx.x;
    const int bx = blockIdx.x, by = blockIdx.y;
    const float* Ab = A + by*128*K;
    const float* Bb = B + bx*128*K;
    const int lr = t >> 2;          // 0..63
    const int lc = (t & 3) << 2;    // 0,4,8,12

    float4 pa0, pa1, pb0, pb1;
    auto ldg = [&](int kt) {
        const float* ap = Ab + lr*K + kt*16 + lc;
        pa0 = *(const float4*)(ap);
        pa1 = *(const float4*)(ap + 64*K);
        const float* bp = Bb + lr*K + kt*16 + lc;
        pb0 = *(const float4*)(bp);
        pb1 = *(const float4*)(bp + 64*K);
    };
    auto sts = [&]() {
        As[lc+0][lr]    = pa0.x; As[lc+1][lr]    = pa0.y; As[lc+2][lr]    = pa0.z; As[lc+3][lr]    = pa0.w;
        As[lc+0][lr+64] = pa1.x; As[lc+1][lr+64] = pa1.y; As[lc+2][lr+64] = pa1.z; As[lc+3][lr+64] = pa1.w;
        Bs[lc+0][lr]    = pb0.x; Bs[lc+1][lr]    = pb0.y; Bs[lc+2][lr]    = pb0.z; Bs[lc+3][lr]    = pb0.w;
        Bs[lc+0][lr+64] = pb1.x; Bs[lc+1][lr+64] = pb1.y; Bs[lc+2][lr+64] = pb1.z; Bs[lc+3][lr+64] = pb1.w;
    };

    float acc[8][8];
    #pragma unroll
    for (int i = 0; i < 8; i++)
        #pragma unroll
        for (int j = 0; j < 8; j++) acc[i][j] = 0.f;

    const int tr = t >> 4, tc = t & 15;
    auto compute = [&]() {
        #pragma unroll
        for (int k = 0; k < 16; k++) {
            float4 a0 = *(const float4*)&As[k][tr*8];
            float4 a1 = *(const float4*)&As[k][tr*8+4];
            float4 b0 = *(const float4*)&Bs[k][tc*8];
            float4 b1 = *(const float4*)&Bs[k][tc*8+4];
            float ar[8] = {a0.x,a0.y,a0.z,a0.w,a1.x,a1.y,a1.z,a1.w};
            float br[8] = {b0.x,b0.y,b0.z,b0.w,b1.x,b1.y,b1.z,b1.w};
            #pragma unroll
            for (int i = 0; i < 8; i++)
                #pragma unroll
                for (int j = 0; j < 8; j++) acc[i][j] += ar[i]*br[j];
        }
    };

    const int nkt = K >> 4;
    ldg(0);
    sts();
    __syncthreads();
    for (int kt = 1; kt < nkt; ++kt) {
        ldg(kt);
        compute();
        __syncthreads();
        sts();
        __syncthreads();
    }
    compute();

    // epilogue
    #pragma unroll
    for (int i = 0; i < 8; i++) {
        int row = by*128 + tr*8 + i;
        float* cp = C + row*N + bx*128 + tc*8;
        float4 r0 = make_float4(acc[i][0], acc[i][1], acc[i][2], acc[i][3]);
        float4 r1 = make_float4(acc[i][4], acc[i][5], acc[i][6], acc[i][7]);
        if (R) {
            const float* rp = R + row*N + bx*128 + tc*8;
            float4 q0 = *(const float4*)rp;
            float4 q1 = *(const float4*)(rp + 4);
            r0.x += q0.x; r0.y += q0.y; r0.z += q0.z; r0.w += q0.w;
            r1.x += q1.x; r1.y += q1.y; r1.z += q1.z; r1.w += q1.w;
        }
        *(float4*)cp       = r0;
        *(float4*)(cp + 4) = r1;
    }
}

// ---------------- RoPE (in-place, interleaved pairs) --------------------------
__global__ __launch_bounds__(256) void rope_kernel(float* __restrict__ q)
{
    int idx = blockIdx.x*256 + threadIdx.x;   // pair index over [B][S][H][32]
    int i = idx & 31;
    int h = (idx >> 5) & 15;
    int s = (idx >> 9) & 2047;
    int b = idx >> 20;
    int off = ((b*SEQ + s)*NHEAD + h)*HDIM + 2*i;
    // inv_freq = 10000^(-i/32); angle in double to keep sin/cos of big args tight
    double inv = exp(-(double)i * (9.210340371976184 / 32.0));
    double ang = (double)s * inv;
    float c  = (float)cos(ang);
    float sn = (float)sin(ang);
    float x1 = q[off], x2 = q[off+1];
    q[off]   = x1*c  - x2*sn;
    q[off+1] = x1*sn + x2*c;
}

// ---------------- causal flash attention, fp32, 64x64 tiles ------------------
// layouts in smem: Qt[d][r], KP[d][c] (K^T) reused as P^T[c][r], Vs[c][j]
__global__ __launch_bounds__(256) void attn_kernel(const float* __restrict__ Q,
    const float* __restrict__ Kg, const float* __restrict__ Vg, float* __restrict__ O)
{
    __shared__ float Qt[64][64];
    __shared__ float KP[64][64];
    __shared__ float Vs[64][64];
    const int t  = threadIdx.x;
    const int qt = blockIdx.x;
    const int bh = blockIdx.y;
    const int b = bh >> 4, h = bh & 15;
    const int base = (b*SEQ)*D_MODEL + h*HDIM;
    const int lr = t >> 2;

    { // load Q tile transposed
        const float* qp = Q + base + (qt*64 + lr)*D_MODEL;
        #pragma unroll
        for (int j = 0; j < 4; j++) {
            int c = ((t & 3) + j*4)*4;
            float4 v = *(const float4*)(qp + c);
            Qt[c+0][lr] = v.x; Qt[c+1][lr] = v.y; Qt[c+2][lr] = v.z; Qt[c+3][lr] = v.w;
        }
    }
    const int tr = t >> 4, tc = t & 15;
    float m[4], l[4], o[4][4];
    #pragma unroll
    for (int a = 0; a < 4; a++) {
        m[a] = -INFINITY; l[a] = 0.f;
        #pragma unroll
        for (int bb = 0; bb < 4; bb++) o[a][bb] = 0.f;
    }
    __syncthreads();

    for (int kt = 0; kt <= qt; ++kt) {
        { // load K^T and V tiles
            const float* kp = Kg + base + (kt*64 + lr)*D_MODEL;
            const float* vp = Vg + base + (kt*64 + lr)*D_MODEL;
            #pragma unroll
            for (int j = 0; j < 4; j++) {
                int c = ((t & 3) + j*4)*4;
                float4 kv = *(const float4*)(kp + c);
                KP[c+0][lr] = kv.x; KP[c+1][lr] = kv.y; KP[c+2][lr] = kv.z; KP[c+3][lr] = kv.w;
                *(float4*)&Vs[lr][c] = *(const float4*)(vp + c);
            }
        }
        __syncthreads();

        // S = Q K^T (4x4 outer products)
        float s[4][4];
        #pragma unroll
        for (int a = 0; a < 4; a++)
            #pragma unroll
            for (int bb = 0; bb < 4; bb++) s[a][bb] = 0.f;
        #pragma unroll 8
        for (int d = 0; d < 64; d++) {
            float4 qv = *(const float4*)&Qt[d][tr*4];
            float4 kv = *(const float4*)&KP[d][tc*4];
            float qa[4] = {qv.x,qv.y,qv.z,qv.w};
            float kb[4] = {kv.x,kv.y,kv.z,kv.w};
            #pragma unroll
            for (int a = 0; a < 4; a++)
                #pragma unroll
                for (int bb = 0; bb < 4; bb++) s[a][bb] += qa[a]*kb[bb];
        }

        // scale, causal mask, online softmax
        #pragma unroll
        for (int a = 0; a < 4; a++) {
            int qrow = qt*64 + tr*4 + a;
            float rmax = -INFINITY;
            #pragma unroll
            for (int bb = 0; bb < 4; bb++) {
                int kcol = kt*64 + tc*4 + bb;
                float sv = s[a][bb]*0.125f;
                if (kcol > qrow) sv = -INFINITY;
                s[a][bb] = sv;
                rmax = fmaxf(rmax, sv);
            }
            #pragma unroll
            for (int off = 8; off; off >>= 1)
                rmax = fmaxf(rmax, __shfl_xor_sync(0xffffffffu, rmax, off));
            float mn = fmaxf(m[a], rmax);
            float alpha = expf(m[a] - mn);
            float rsum = 0.f;
            #pragma unroll
            for (int bb = 0; bb < 4; bb++) {
                float p = expf(s[a][bb] - mn);
                s[a][bb] = p;
                rsum += p;
            }
            #pragma unroll
            for (int off = 8; off; off >>= 1)
                rsum += __shfl_xor_sync(0xffffffffu, rsum, off);
            l[a] = l[a]*alpha + rsum;
            m[a] = mn;
            #pragma unroll
            for (int bb = 0; bb < 4; bb++) o[a][bb] *= alpha;
        }
        __syncthreads();  // all S-reads of KP done

        // write P^T over K^T
        #pragma unroll
        for (int bb = 0; bb < 4; bb++)
            *(float4*)&KP[tc*4+bb][tr*4] = make_float4(s[0][bb], s[1][bb], s[2][bb], s[3][bb]);
        __syncthreads();

        // O += P V
        #pragma unroll 8
        for (int c = 0; c < 64; c++) {
            float4 pv = *(const float4*)&KP[c][tr*4];
            float4 vv = *(const float4*)&Vs[c][tc*4];
            float pa[4] = {pv.x,pv.y,pv.z,pv.w};
            float vb[4] = {vv.x,vv.y,vv.z,vv.w};
            #pragma unroll
            for (int a = 0; a < 4; a++)
                #pragma unroll
                for (int bb = 0; bb < 4; bb++) o[a][bb] += pa[a]*vb[bb];
        }
        __syncthreads();
    }

    #pragma unroll
    for (int a = 0; a < 4; a++) {
        float invl = 1.f/l[a];
        float4 r = make_float4(o[a][0]*invl, o[a][1]*invl, o[a][2]*invl, o[a][3]*invl);
        *(float4*)(O + base + (qt*64 + tr*4 + a)*D_MODEL + tc*4) = r;
    }
}

// ---------------- SiLU(g) * u, in place into g -------------------------------
__global__ __launch_bounds__(256) void silu_mul_kernel(float* __restrict__ g,
        const float* __restrict__ u, int n4)
{
    int i = blockIdx.x*256 + threadIdx.x;
    if (i < n4) {
        float4 gv = ((float4*)g)[i];
        float4 uv = ((const float4*)u)[i];
        gv.x = gv.x/(1.f+expf(-gv.x))*uv.x;
        gv.y = gv.y/(1.f+expf(-gv.y))*uv.y;
        gv.z = gv.z/(1.f+expf(-gv.z))*uv.z;
        gv.w = gv.w/(1.f+expf(-gv.w))*uv.w;
        ((float4*)g)[i] = gv;
    }
}

// ---------------- launch -----------------------------------------------------
extern "C" void kernel_launch(void* const* d_in, const int* in_sizes, int n_in,
                              void* d_out, int out_size)
{
    const float* x   = (const float*)d_in[0];
    // d_in[1] = num_heads (int, fixed 16)
    const float* wq  = (const float*)d_in[2];
    const float* wk  = (const float*)d_in[3];
    const float* wv  = (const float*)d_in[4];
    const float* wo  = (const float*)d_in[5];
    const float* ln1 = (const float*)d_in[6];
    const float* ln2 = (const float*)d_in[7];
    const float* w1  = (const float*)d_in[8];
    const float* w2  = (const float*)d_in[9];
    const float* w3  = (const float*)d_in[10];
    float* out = (float*)d_out;

    float *xn,*qb,*kb,*vb,*ob,*x1,*xn2,*gb,*ub;
    cudaGetSymbolAddress((void**)&xn,  g_xn);
    cudaGetSymbolAddress((void**)&qb,  g_q);
    cudaGetSymbolAddress((void**)&kb,  g_k);
    cudaGetSymbolAddress((void**)&vb,  g_v);
    cudaGetSymbolAddress((void**)&ob,  g_o);
    cudaGetSymbolAddress((void**)&x1,  g_x1);
    cudaGetSymbolAddress((void**)&xn2, g_xn2);
    cudaGetSymbolAddress((void**)&gb,  g_g);
    cudaGetSymbolAddress((void**)&ub,  g_u);

    dim3 g1(D_MODEL/128, BS/128);  // (8, 32)
    dim3 g2(D_FF/128,    BS/128);  // (32, 32)

    rmsnorm_kernel<<<BS, 256>>>(x, ln1, xn);
    sgemm_nt<<<g1, 256>>>(xn, wq, nullptr, qb, BS, D_MODEL, D_MODEL);
    sgemm_nt<<<g1, 256>>>(xn, wk, nullptr, kb, BS, D_MODEL, D_MODEL);
    sgemm_nt<<<g1, 256>>>(xn, wv, nullptr, vb, BS, D_MODEL, D_MODEL);
    rope_kernel<<<(BS*NHEAD*32)/256, 256>>>(qb);
    rope_kernel<<<(BS*NHEAD*32)/256, 256>>>(kb);
    attn_kernel<<<dim3(SEQ/64, BATCH*NHEAD), 256>>>(qb, kb, vb, ob);
    sgemm_nt<<<g1, 256>>>(ob, wo, x, x1, BS, D_MODEL, D_MODEL);
    rmsnorm_kernel<<<BS, 256>>>(x1, ln2, xn2);
    sgemm_nt<<<g2, 256>>>(xn2, w1, nullptr, gb, BS, D_FF, D_MODEL);
    sgemm_nt<<<g2, 256>>>(xn2, w3, nullptr, ub, BS, D_FF, D_MODEL);
    silu_mul_kernel<<<(BS*D_FF/4)/256, 256>>>(gb, ub, BS*D_FF/4);
    sgemm_nt<<<g1, 256>>>(gb, w2, x1, out, BS, D_MODEL, D_FF);
}

// round 3
// speedup vs baseline: 1.6282x; 1.6282x over previous
#include <cuda_runtime.h>
#include <cuda_bf16.h>
#include <math.h>
#include <cstdint>

#define D_MODEL 1024
#define D_FF    4096
#define BATCH   2
#define SEQ     2048
#define NHEAD   16
#define HDIM    64
#define BS      (BATCH*SEQ)   // 4096 rows

// ---------------- scratch (device globals; no allocations allowed) ----------
__device__ float g_xn [BS*D_MODEL];
__device__ float g_q  [BS*D_MODEL];
__device__ float g_k  [BS*D_MODEL];
__device__ float g_v  [BS*D_MODEL];
__device__ float g_o  [BS*D_MODEL];
__device__ float g_x1 [BS*D_MODEL];
__device__ float g_xn2[BS*D_MODEL];
__device__ float g_g  [BS*D_FF];
__device__ float g_u  [BS*D_FF];

// ================= helpers ===================================================
__device__ __forceinline__ uint32_t smem_to_u32(const void* p) {
    uint32_t a;
    asm("{ .reg .u64 t; cvta.to.shared.u64 t, %1; cvt.u32.u64 %0, t; }" : "=r"(a) : "l"(p));
    return a;
}
__device__ __forceinline__ void ldsm4(uint32_t* r, uint32_t addr) {
    asm volatile("ldmatrix.sync.aligned.m8n8.x4.shared.b16 {%0,%1,%2,%3}, [%4];"
                 : "=r"(r[0]), "=r"(r[1]), "=r"(r[2]), "=r"(r[3]) : "r"(addr));
}
__device__ __forceinline__ void mma16816(float* d, const uint32_t* a, const uint32_t* b) {
    asm volatile("mma.sync.aligned.m16n8k16.row.col.f32.bf16.bf16.f32 "
                 "{%0,%1,%2,%3}, {%4,%5,%6,%7}, {%8,%9}, {%0,%1,%2,%3};"
                 : "+f"(d[0]), "+f"(d[1]), "+f"(d[2]), "+f"(d[3])
                 : "r"(a[0]), "r"(a[1]), "r"(a[2]), "r"(a[3]), "r"(b[0]), "r"(b[1]));
}
__device__ __forceinline__ uint32_t swz(uint32_t off) {   // SW128: chunk ^= row&7
    return off ^ ((off >> 3) & 0x70);
}
__device__ __forceinline__ uint32_t pack_bf2(__nv_bfloat16 a, __nv_bfloat16 b) {
    return ((uint32_t)__bfloat16_as_ushort(b) << 16) | (uint32_t)__bfloat16_as_ushort(a);
}
// split 4 consecutive fp32 K-elems into bf16 hi/lo, store 8B to each tile
__device__ __forceinline__ void split_sts(uint32_t phi, uint32_t plo, float4 v) {
    __nv_bfloat16 hx = __float2bfloat16(v.x), hy = __float2bfloat16(v.y);
    __nv_bfloat16 hz = __float2bfloat16(v.z), hw = __float2bfloat16(v.w);
    __nv_bfloat16 lx = __float2bfloat16(v.x - __bfloat162float(hx));
    __nv_bfloat16 ly = __float2bfloat16(v.y - __bfloat162float(hy));
    __nv_bfloat16 lz = __float2bfloat16(v.z - __bfloat162float(hz));
    __nv_bfloat16 lw = __float2bfloat16(v.w - __bfloat162float(hw));
    uint32_t h0 = pack_bf2(hx, hy), h1 = pack_bf2(hz, hw);
    uint32_t l0 = pack_bf2(lx, ly), l1 = pack_bf2(lz, lw);
    asm volatile("st.shared.v2.b32 [%0], {%1, %2};" :: "r"(phi), "r"(h0), "r"(h1) : "memory");
    asm volatile("st.shared.v2.b32 [%0], {%1, %2};" :: "r"(plo), "r"(l0), "r"(l1) : "memory");
}

// ================= HMMA split-bf16 GEMM NT ==================================
// C[M,N] = A[M,K] * B[N,K]^T (+ optional residual R), fp32 in/out.
// x = hi + lo (bf16 pair); D += Ahi*Bhi + Ahi*Blo + Alo*Bhi  (err ~2^-18).
// CTA 128x128, K-chunk 64 (128B bf16 rows, SW128 swizzle), 2-stage pipeline.
#define TILE_B   16384                 // one 128x64 bf16 tile
#define STAGE_B  (4*TILE_B)            // Ahi, Alo, Bhi, Blo
#define GEMM_SMEM (2*STAGE_B)          // 131072

__global__ void __launch_bounds__(256)
hmma_gemm(const float* __restrict__ A, const float* __restrict__ B,
          const float* __restrict__ R, float* __restrict__ C,
          int M, int N, int K)
{
    extern __shared__ char smem[];
    const uint32_t sb = smem_to_u32(smem);
    const int t = threadIdx.x, wid = t >> 5, l = t & 31;
    const int m0 = blockIdx.y * 128, n0 = blockIdx.x * 128;
    const int wm = (wid & 1) * 64;     // warp M offset (2 warps in M)
    const int wn = (wid >> 1) * 32;    // warp N offset (4 warps in N)

    const int ldr = t >> 4;            // 0..127: row handled for ldg/sts slice i=0
    const int ldq = t & 15;            // col quad (4 fp32)

    float4 aR[8], bR[8];
    auto ldg = [&](int c) {
        const float* Ab = A + (size_t)m0 * K + c * 64;
        const float* Bb = B + (size_t)n0 * K + c * 64;
        #pragma unroll
        for (int i = 0; i < 8; i++) {
            int f = i * 256 + t; int r = f >> 4, q = f & 15;
            aR[i] = *(const float4*)(Ab + (size_t)r * K + q * 4);
            bR[i] = *(const float4*)(Bb + (size_t)r * K + q * 4);
        }
    };
    auto sts = [&](int s) {
        const uint32_t stg = sb + s * STAGE_B;
        #pragma unroll
        for (int i = 0; i < 8; i++) {
            int f = i * 256 + t; int r = f >> 4, q = f & 15;
            uint32_t sw = swz((uint32_t)(r * 128 + q * 8));
            split_sts(stg + sw,            stg + TILE_B + sw,   aR[i]);
            split_sts(stg + 2*TILE_B + sw, stg + 3*TILE_B + sw, bR[i]);
        }
    };

    float acc[4][4][4];
    #pragma unroll
    for (int mt = 0; mt < 4; mt++)
        #pragma unroll
        for (int nt = 0; nt < 4; nt++)
            #pragma unroll
            for (int r = 0; r < 4; r++) acc[mt][nt][r] = 0.f;

    // ldmatrix source offsets (unswizzled): A row/chunk, B row/chunk
    const int arow = wm + (l & 15);          // + mt*16
    const int achk = (l >> 4);               // + 2k
    const int brow = wn + ((l >> 4) << 3) + (l & 7);  // + p*16
    const int bchk = (l >> 3) & 1;           // + 2k

    auto compute = [&](int s) {
        const uint32_t stg = sb + s * STAGE_B;
        #pragma unroll
        for (int k = 0; k < 4; k++) {
            uint32_t ah[4][4], al[4][4], bh[2][4], bl[2][4];
            #pragma unroll
            for (int mt = 0; mt < 4; mt++) {
                uint32_t off = swz((uint32_t)((arow + mt*16) * 128 + (achk + 2*k) * 16));
                ldsm4(ah[mt], stg + off);
                ldsm4(al[mt], stg + TILE_B + off);
            }
            #pragma unroll
            for (int p = 0; p < 2; p++) {
                uint32_t off = swz((uint32_t)((brow + p*16) * 128 + (bchk + 2*k) * 16));
                ldsm4(bh[p], stg + 2*TILE_B + off);
                ldsm4(bl[p], stg + 3*TILE_B + off);
            }
            #pragma unroll
            for (int mt = 0; mt < 4; mt++)
                #pragma unroll
                for (int nt = 0; nt < 4; nt++) {
                    const uint32_t* bhp = &bh[nt >> 1][(nt & 1) * 2];
                    const uint32_t* blp = &bl[nt >> 1][(nt & 1) * 2];
                    mma16816(acc[mt][nt], ah[mt], bhp);
                    mma16816(acc[mt][nt], ah[mt], blp);
                    mma16816(acc[mt][nt], al[mt], bhp);
                }
        }
    };

    const int nchunks = K >> 6;
    ldg(0);
    sts(0);
    __syncthreads();
    for (int c = 0; c < nchunks; ++c) {
        if (c + 1 < nchunks) ldg(c + 1);
        compute(c & 1);
        __syncthreads();
        if (c + 1 < nchunks) {
            sts((c + 1) & 1);
            __syncthreads();
        }
    }

    // epilogue: d layout row=(l>>2)+{0,8}, col=(l&3)*2+{0,1} per 16x8 tile
    #pragma unroll
    for (int mt = 0; mt < 4; mt++)
        #pragma unroll
        for (int nt = 0; nt < 4; nt++)
            #pragma unroll
            for (int h = 0; h < 2; h++) {
                int row = m0 + wm + mt*16 + (l >> 2) + h*8;
                int col = n0 + wn + nt*8 + (l & 3)*2;
                float2 v = make_float2(acc[mt][nt][h*2], acc[mt][nt][h*2+1]);
                if (R) {
                    const float2 q = *(const float2*)(R + (size_t)row * N + col);
                    v.x += q.x; v.y += q.y;
                }
                *(float2*)(C + (size_t)row * N + col) = v;
            }
}

// ---------------- RMSNorm: one block per row ---------------------------------
__global__ __launch_bounds__(256) void rmsnorm_kernel(const float* __restrict__ x,
        const float* __restrict__ w, float* __restrict__ out)
{
    const int row = blockIdx.x;
    const int t   = threadIdx.x;
    const float4 v = *(const float4*)(x + row*D_MODEL + t*4);
    float ss = v.x*v.x + v.y*v.y + v.z*v.z + v.w*v.w;
    #pragma unroll
    for (int off = 16; off; off >>= 1) ss += __shfl_xor_sync(0xffffffffu, ss, off);
    __shared__ float red[8];
    if ((t & 31) == 0) red[t >> 5] = ss;
    __syncthreads();
    float tot = red[0]+red[1]+red[2]+red[3]+red[4]+red[5]+red[6]+red[7];
    float inv = rsqrtf(tot * (1.0f/D_MODEL) + 1e-5f);
    const float4 wv = *(const float4*)(w + t*4);
    float4 o;
    o.x = v.x*inv*wv.x; o.y = v.y*inv*wv.y; o.z = v.z*inv*wv.z; o.w = v.w*inv*wv.w;
    *(float4*)(out + row*D_MODEL + t*4) = o;
}

// ---------------- RoPE (in-place, interleaved pairs) --------------------------
__global__ __launch_bounds__(256) void rope_kernel(float* __restrict__ q)
{
    int idx = blockIdx.x*256 + threadIdx.x;   // pair index over [B][S][H][32]
    int i = idx & 31;
    int h = (idx >> 5) & 15;
    int s = (idx >> 9) & 2047;
    int b = idx >> 20;
    int off = ((b*SEQ + s)*NHEAD + h)*HDIM + 2*i;
    double inv = exp(-(double)i * (9.210340371976184 / 32.0));
    double ang = (double)s * inv;
    float c  = (float)cos(ang);
    float sn = (float)sin(ang);
    float x1 = q[off], x2 = q[off+1];
    q[off]   = x1*c  - x2*sn;
    q[off+1] = x1*sn + x2*c;
}

// ---------------- causal flash attention, fp32, 64x64 tiles ------------------
__global__ __launch_bounds__(256) void attn_kernel(const float* __restrict__ Q,
    const float* __restrict__ Kg, const float* __restrict__ Vg, float* __restrict__ O)
{
    __shared__ float Qt[64][64];
    __shared__ float KP[64][64];
    __shared__ float Vs[64][64];
    const int t  = threadIdx.x;
    const int qt = blockIdx.x;
    const int bh = blockIdx.y;
    const int b = bh >> 4, h = bh & 15;
    const int base = (b*SEQ)*D_MODEL + h*HDIM;
    const int lr = t >> 2;

    {
        const float* qp = Q + base + (qt*64 + lr)*D_MODEL;
        #pragma unroll
        for (int j = 0; j < 4; j++) {
            int c = ((t & 3) + j*4)*4;
            float4 v = *(const float4*)(qp + c);
            Qt[c+0][lr] = v.x; Qt[c+1][lr] = v.y; Qt[c+2][lr] = v.z; Qt[c+3][lr] = v.w;
        }
    }
    const int tr = t >> 4, tc = t & 15;
    float m[4], l[4], o[4][4];
    #pragma unroll
    for (int a = 0; a < 4; a++) {
        m[a] = -INFINITY; l[a] = 0.f;
        #pragma unroll
        for (int bb = 0; bb < 4; bb++) o[a][bb] = 0.f;
    }
    __syncthreads();

    for (int kt = 0; kt <= qt; ++kt) {
        {
            const float* kp = Kg + base + (kt*64 + lr)*D_MODEL;
            const float* vp = Vg + base + (kt*64 + lr)*D_MODEL;
            #pragma unroll
            for (int j = 0; j < 4; j++) {
                int c = ((t & 3) + j*4)*4;
                float4 kv = *(const float4*)(kp + c);
                KP[c+0][lr] = kv.x; KP[c+1][lr] = kv.y; KP[c+2][lr] = kv.z; KP[c+3][lr] = kv.w;
                *(float4*)&Vs[lr][c] = *(const float4*)(vp + c);
            }
        }
        __syncthreads();

        float s[4][4];
        #pragma unroll
        for (int a = 0; a < 4; a++)
            #pragma unroll
            for (int bb = 0; bb < 4; bb++) s[a][bb] = 0.f;
        #pragma unroll 8
        for (int d = 0; d < 64; d++) {
            float4 qv = *(const float4*)&Qt[d][tr*4];
            float4 kv = *(const float4*)&KP[d][tc*4];
            float qa[4] = {qv.x,qv.y,qv.z,qv.w};
            float kb[4] = {kv.x,kv.y,kv.z,kv.w};
            #pragma unroll
            for (int a = 0; a < 4; a++)
                #pragma unroll
                for (int bb = 0; bb < 4; bb++) s[a][bb] += qa[a]*kb[bb];
        }

        #pragma unroll
        for (int a = 0; a < 4; a++) {
            int qrow = qt*64 + tr*4 + a;
            float rmax = -INFINITY;
            #pragma unroll
            for (int bb = 0; bb < 4; bb++) {
                int kcol = kt*64 + tc*4 + bb;
                float sv = s[a][bb]*0.125f;
                if (kcol > qrow) sv = -INFINITY;
                s[a][bb] = sv;
                rmax = fmaxf(rmax, sv);
            }
            #pragma unroll
            for (int off = 8; off; off >>= 1)
                rmax = fmaxf(rmax, __shfl_xor_sync(0xffffffffu, rmax, off));
            float mn = fmaxf(m[a], rmax);
            float alpha = expf(m[a] - mn);
            float rsum = 0.f;
            #pragma unroll
            for (int bb = 0; bb < 4; bb++) {
                float p = expf(s[a][bb] - mn);
                s[a][bb] = p;
                rsum += p;
            }
            #pragma unroll
            for (int off = 8; off; off >>= 1)
                rsum += __shfl_xor_sync(0xffffffffu, rsum, off);
            l[a] = l[a]*alpha + rsum;
            m[a] = mn;
            #pragma unroll
            for (int bb = 0; bb < 4; bb++) o[a][bb] *= alpha;
        }
        __syncthreads();

        #pragma unroll
        for (int bb = 0; bb < 4; bb++)
            *(float4*)&KP[tc*4+bb][tr*4] = make_float4(s[0][bb], s[1][bb], s[2][bb], s[3][bb]);
        __syncthreads();

        #pragma unroll 8
        for (int c = 0; c < 64; c++) {
            float4 pv = *(const float4*)&KP[c][tr*4];
            float4 vv = *(const float4*)&Vs[c][tc*4];
            float pa[4] = {pv.x,pv.y,pv.z,pv.w};
            float vb[4] = {vv.x,vv.y,vv.z,vv.w};
            #pragma unroll
            for (int a = 0; a < 4; a++)
                #pragma unroll
                for (int bb = 0; bb < 4; bb++) o[a][bb] += pa[a]*vb[bb];
        }
        __syncthreads();
    }

    #pragma unroll
    for (int a = 0; a < 4; a++) {
        float invl = 1.f/l[a];
        float4 r = make_float4(o[a][0]*invl, o[a][1]*invl, o[a][2]*invl, o[a][3]*invl);
        *(float4*)(O + base + (qt*64 + tr*4 + a)*D_MODEL + tc*4) = r;
    }
}

// ---------------- SiLU(g) * u, in place into g -------------------------------
__global__ __launch_bounds__(256) void silu_mul_kernel(float* __restrict__ g,
        const float* __restrict__ u, int n4)
{
    int i = blockIdx.x*256 + threadIdx.x;
    if (i < n4) {
        float4 gv = ((float4*)g)[i];
        float4 uv = ((const float4*)u)[i];
        gv.x = gv.x/(1.f+expf(-gv.x))*uv.x;
        gv.y = gv.y/(1.f+expf(-gv.y))*uv.y;
        gv.z = gv.z/(1.f+expf(-gv.z))*uv.z;
        gv.w = gv.w/(1.f+expf(-gv.w))*uv.w;
        ((float4*)g)[i] = gv;
    }
}

// ---------------- launch -----------------------------------------------------
extern "C" void kernel_launch(void* const* d_in, const int* in_sizes, int n_in,
                              void* d_out, int out_size)
{
    const float* x   = (const float*)d_in[0];
    const float* wq  = (const float*)d_in[2];
    const float* wk  = (const float*)d_in[3];
    const float* wv  = (const float*)d_in[4];
    const float* wo  = (const float*)d_in[5];
    const float* ln1 = (const float*)d_in[6];
    const float* ln2 = (const float*)d_in[7];
    const float* w1  = (const float*)d_in[8];
    const float* w2  = (const float*)d_in[9];
    const float* w3  = (const float*)d_in[10];
    float* out = (float*)d_out;

    float *xn,*qb,*kb,*vb,*ob,*x1,*xn2,*gb,*ub;
    cudaGetSymbolAddress((void**)&xn,  g_xn);
    cudaGetSymbolAddress((void**)&qb,  g_q);
    cudaGetSymbolAddress((void**)&kb,  g_k);
    cudaGetSymbolAddress((void**)&vb,  g_v);
    cudaGetSymbolAddress((void**)&ob,  g_o);
    cudaGetSymbolAddress((void**)&x1,  g_x1);
    cudaGetSymbolAddress((void**)&xn2, g_xn2);
    cudaGetSymbolAddress((void**)&gb,  g_g);
    cudaGetSymbolAddress((void**)&ub,  g_u);

    cudaFuncSetAttribute(hmma_gemm, cudaFuncAttributeMaxDynamicSharedMemorySize, GEMM_SMEM);

    dim3 gD(D_MODEL/128, BS/128);  // (8, 32)
    dim3 gF(D_FF/128,    BS/128);  // (32, 32)

    rmsnorm_kernel<<<BS, 256>>>(x, ln1, xn);
    hmma_gemm<<<gD, 256, GEMM_SMEM>>>(xn, wq, nullptr, qb, BS, D_MODEL, D_MODEL);
    hmma_gemm<<<gD, 256, GEMM_SMEM>>>(xn, wk, nullptr, kb, BS, D_MODEL, D_MODEL);
    hmma_gemm<<<gD, 256, GEMM_SMEM>>>(xn, wv, nullptr, vb, BS, D_MODEL, D_MODEL);
    rope_kernel<<<(BS*NHEAD*32)/256, 256>>>(qb);
    rope_kernel<<<(BS*NHEAD*32)/256, 256>>>(kb);
    attn_kernel<<<dim3(SEQ/64, BATCH*NHEAD), 256>>>(qb, kb, vb, ob);
    hmma_gemm<<<gD, 256, GEMM_SMEM>>>(ob, wo, x, x1, BS, D_MODEL, D_MODEL);
    rmsnorm_kernel<<<BS, 256>>>(x1, ln2, xn2);
    hmma_gemm<<<gF, 256, GEMM_SMEM>>>(xn2, w1, nullptr, gb, BS, D_FF, D_MODEL);
    hmma_gemm<<<gF, 256, GEMM_SMEM>>>(xn2, w3, nullptr, ub, BS, D_FF, D_MODEL);
    silu_mul_kernel<<<(BS*D_FF/4)/256, 256>>>(gb, ub, BS*D_FF/4);
    hmma_gemm<<<gD, 256, GEMM_SMEM>>>(gb, w2, x1, out, BS, D_MODEL, D_FF);
}

// round 4
// speedup vs baseline: 2.0924x; 1.2851x over previous
#include <cuda_runtime.h>
#include <cuda_bf16.h>
#include <math.h>
#include <cstdint>

#define D_MODEL 1024
#define D_FF    4096
#define BATCH   2
#define SEQ     2048
#define NHEAD   16
#define HDIM    64
#define BS      (BATCH*SEQ)   // 4096 rows

// ---------------- scratch (device globals; no allocations allowed) ----------
// fp32 intermediates
__device__ float g_q  [BS*D_MODEL];
__device__ float g_k  [BS*D_MODEL];
__device__ float g_v  [BS*D_MODEL];
__device__ float g_x1 [BS*D_MODEL];
__device__ float g_g  [BS*D_FF];
__device__ float g_u  [BS*D_FF];
// pre-split bf16 hi/lo activations
__device__ __nv_bfloat16 s_xn_h [BS*D_MODEL], s_xn_l [BS*D_MODEL];
__device__ __nv_bfloat16 s_o_h  [BS*D_MODEL], s_o_l  [BS*D_MODEL];
__device__ __nv_bfloat16 s_xn2_h[BS*D_MODEL], s_xn2_l[BS*D_MODEL];
__device__ __nv_bfloat16 s_h_h  [BS*D_FF],    s_h_l  [BS*D_FF];
// pre-split bf16 hi/lo weights
__device__ __nv_bfloat16 s_wq_h[D_MODEL*D_MODEL], s_wq_l[D_MODEL*D_MODEL];
__device__ __nv_bfloat16 s_wk_h[D_MODEL*D_MODEL], s_wk_l[D_MODEL*D_MODEL];
__device__ __nv_bfloat16 s_wv_h[D_MODEL*D_MODEL], s_wv_l[D_MODEL*D_MODEL];
__device__ __nv_bfloat16 s_wo_h[D_MODEL*D_MODEL], s_wo_l[D_MODEL*D_MODEL];
__device__ __nv_bfloat16 s_w1_h[D_FF*D_MODEL],    s_w1_l[D_FF*D_MODEL];
__device__ __nv_bfloat16 s_w3_h[D_FF*D_MODEL],    s_w3_l[D_FF*D_MODEL];
__device__ __nv_bfloat16 s_w2_h[D_MODEL*D_FF],    s_w2_l[D_MODEL*D_FF];

// ================= helpers ===================================================
__device__ __forceinline__ uint32_t smem_to_u32(const void* p) {
    uint32_t a;
    asm("{ .reg .u64 t; cvta.to.shared.u64 t, %1; cvt.u32.u64 %0, t; }" : "=r"(a) : "l"(p));
    return a;
}
__device__ __forceinline__ void ldsm4(uint32_t* r, uint32_t addr) {
    asm volatile("ldmatrix.sync.aligned.m8n8.x4.shared.b16 {%0,%1,%2,%3}, [%4];"
                 : "=r"(r[0]), "=r"(r[1]), "=r"(r[2]), "=r"(r[3]) : "r"(addr));
}
__device__ __forceinline__ void mma16816(float* d, const uint32_t* a, const uint32_t* b) {
    asm volatile("mma.sync.aligned.m16n8k16.row.col.f32.bf16.bf16.f32 "
                 "{%0,%1,%2,%3}, {%4,%5,%6,%7}, {%8,%9}, {%0,%1,%2,%3};"
                 : "+f"(d[0]), "+f"(d[1]), "+f"(d[2]), "+f"(d[3])
                 : "r"(a[0]), "r"(a[1]), "r"(a[2]), "r"(a[3]), "r"(b[0]), "r"(b[1]));
}
__device__ __forceinline__ uint32_t swz(uint32_t off) {   // SW128
    return off ^ ((off >> 3) & 0x70);
}
__device__ __forceinline__ uint32_t pack_bf2(__nv_bfloat16 a, __nv_bfloat16 b) {
    return ((uint32_t)__bfloat16_as_ushort(b) << 16) | (uint32_t)__bfloat16_as_ushort(a);
}
__device__ __forceinline__ void split4(float4 v, uint2& h, uint2& l) {
    __nv_bfloat16 hx = __float2bfloat16(v.x), hy = __float2bfloat16(v.y);
    __nv_bfloat16 hz = __float2bfloat16(v.z), hw = __float2bfloat16(v.w);
    h.x = pack_bf2(hx, hy); h.y = pack_bf2(hz, hw);
    l.x = pack_bf2(__float2bfloat16(v.x - __bfloat162float(hx)),
                   __float2bfloat16(v.y - __bfloat162float(hy)));
    l.y = pack_bf2(__float2bfloat16(v.z - __bfloat162float(hz)),
                   __float2bfloat16(v.w - __bfloat162float(hw)));
}
__device__ __forceinline__ void cp16(uint32_t dst, const void* src) {
    asm volatile("cp.async.cg.shared.global [%0], [%1], 16;" :: "r"(dst), "l"(src));
}
#define CP_COMMIT() asm volatile("cp.async.commit_group;" ::: "memory")
#define CP_WAIT2()  asm volatile("cp.async.wait_group 2;" ::: "memory")

// ================= HMMA split-bf16 GEMM NT (pre-split operands) ==============
// C[M,N] = (Ah+Al)[M,K] * (Bh+Bl)[N,K]^T (+R), D += Ah*Bh + Ah*Bl + Al*Bh.
// CTA 128x128, K-chunk 64, SW128 smem, 3-stage cp.async pipeline.
#define TILE_B   16384                 // one 128x64 bf16 tile
#define STAGE_B  (4*TILE_B)            // Ah, Al, Bh, Bl
#define NSTAGE   3
#define GEMM_SMEM (NSTAGE*STAGE_B)     // 196608

__global__ void __launch_bounds__(256)
hmma_gemm(const __nv_bfloat16* __restrict__ Ah, const __nv_bfloat16* __restrict__ Al,
          const __nv_bfloat16* __restrict__ Bh, const __nv_bfloat16* __restrict__ Bl,
          const float* __restrict__ R, float* __restrict__ C,
          int M, int N, int K)
{
    extern __shared__ char smem[];
    const uint32_t sb = smem_to_u32(smem);
    const int t = threadIdx.x, wid = t >> 5, l = t & 31;
    const int m0 = blockIdx.y * 128, n0 = blockIdx.x * 128;
    const int wm = (wid & 1) * 64;     // 2 warps in M
    const int wn = (wid >> 1) * 32;    // 4 warps in N

    // cp.async slice: 4 iters/thread/tile; f = i*256+t -> row f>>3, chunk f&7
    const int cprow = t >> 3;          // +i*32
    const int cpch  = t & 7;
    const uint32_t cpsw = swz((uint32_t)(cprow * 128 + cpch * 16));

    auto issue_cp = [&](int c, int s) {
        const uint32_t stg = sb + s * STAGE_B;
        const size_t koff = (size_t)c * 64 + cpch * 8;
        const __nv_bfloat16* a_h = Ah + (size_t)(m0 + cprow) * K + koff;
        const __nv_bfloat16* a_l = Al + (size_t)(m0 + cprow) * K + koff;
        const __nv_bfloat16* b_h = Bh + (size_t)(n0 + cprow) * K + koff;
        const __nv_bfloat16* b_l = Bl + (size_t)(n0 + cprow) * K + koff;
        #pragma unroll
        for (int i = 0; i < 4; i++) {
            uint32_t d = cpsw + i * 32 * 128;   // +32 rows per iter
            size_t   g = (size_t)i * 32 * K;
            cp16(stg +            d, a_h + g);
            cp16(stg +   TILE_B + d, a_l + g);
            cp16(stg + 2*TILE_B + d, b_h + g);
            cp16(stg + 3*TILE_B + d, b_l + g);
        }
    };

    float acc[4][4][4];
    #pragma unroll
    for (int mt = 0; mt < 4; mt++)
        #pragma unroll
        for (int nt = 0; nt < 4; nt++)
            #pragma unroll
            for (int r = 0; r < 4; r++) acc[mt][nt][r] = 0.f;

    const int arow = wm + (l & 15);
    const int achk = (l >> 4);
    const int brow = wn + ((l >> 4) << 3) + (l & 7);
    const int bchk = (l >> 3) & 1;

    auto compute = [&](int s) {
        const uint32_t stg = sb + s * STAGE_B;
        #pragma unroll
        for (int k = 0; k < 4; k++) {
            uint32_t ah[4][4], al[4][4], bh[2][4], bl[2][4];
            #pragma unroll
            for (int mt = 0; mt < 4; mt++) {
                uint32_t off = swz((uint32_t)((arow + mt*16) * 128 + (achk + 2*k) * 16));
                ldsm4(ah[mt], stg + off);
                ldsm4(al[mt], stg + TILE_B + off);
            }
            #pragma unroll
            for (int p = 0; p < 2; p++) {
                uint32_t off = swz((uint32_t)((brow + p*16) * 128 + (bchk + 2*k) * 16));
                ldsm4(bh[p], stg + 2*TILE_B + off);
                ldsm4(bl[p], stg + 3*TILE_B + off);
            }
            #pragma unroll
            for (int mt = 0; mt < 4; mt++)
                #pragma unroll
                for (int nt = 0; nt < 4; nt++) {
                    const uint32_t* bhp = &bh[nt >> 1][(nt & 1) * 2];
                    const uint32_t* blp = &bl[nt >> 1][(nt & 1) * 2];
                    mma16816(acc[mt][nt], ah[mt], bhp);
                    mma16816(acc[mt][nt], ah[mt], blp);
                    mma16816(acc[mt][nt], al[mt], bhp);
                }
        }
    };

    const int nchunks = K >> 6;
    issue_cp(0, 0); CP_COMMIT();
    issue_cp(1, 1); CP_COMMIT();
    for (int c = 0; c < nchunks; ++c) {
        if (c + 2 < nchunks) issue_cp(c + 2, (c + 2) % NSTAGE);
        CP_COMMIT();                    // always commit to keep group count uniform
        CP_WAIT2();                     // chunk c's group complete
        __syncthreads();
        compute(c % NSTAGE);
        __syncthreads();                // free stage before next iter's issue
    }

    #pragma unroll
    for (int mt = 0; mt < 4; mt++)
        #pragma unroll
        for (int nt = 0; nt < 4; nt++)
            #pragma unroll
            for (int h = 0; h < 2; h++) {
                int row = m0 + wm + mt*16 + (l >> 2) + h*8;
                int col = n0 + wn + nt*8 + (l & 3)*2;
                float2 v = make_float2(acc[mt][nt][h*2], acc[mt][nt][h*2+1]);
                if (R) {
                    const float2 q = *(const float2*)(R + (size_t)row * N + col);
                    v.x += q.x; v.y += q.y;
                }
                *(float2*)(C + (size_t)row * N + col) = v;
            }
}

// ---------------- fp32 -> bf16 hi/lo split (weights) -------------------------
__global__ __launch_bounds__(256) void split_kernel(const float* __restrict__ x,
        __nv_bfloat16* __restrict__ h, __nv_bfloat16* __restrict__ l, int n4)
{
    int i = blockIdx.x*256 + threadIdx.x;
    if (i < n4) {
        float4 v = ((const float4*)x)[i];
        uint2 hh, ll;
        split4(v, hh, ll);
        ((uint2*)h)[i] = hh;
        ((uint2*)l)[i] = ll;
    }
}

// ---------------- RMSNorm -> split bf16 --------------------------------------
__global__ __launch_bounds__(256) void rmsnorm_kernel(const float* __restrict__ x,
        const float* __restrict__ w,
        __nv_bfloat16* __restrict__ oh, __nv_bfloat16* __restrict__ ol)
{
    const int row = blockIdx.x;
    const int t   = threadIdx.x;
    const float4 v = *(const float4*)(x + row*D_MODEL + t*4);
    float ss = v.x*v.x + v.y*v.y + v.z*v.z + v.w*v.w;
    #pragma unroll
    for (int off = 16; off; off >>= 1) ss += __shfl_xor_sync(0xffffffffu, ss, off);
    __shared__ float red[8];
    if ((t & 31) == 0) red[t >> 5] = ss;
    __syncthreads();
    float tot = red[0]+red[1]+red[2]+red[3]+red[4]+red[5]+red[6]+red[7];
    float inv = rsqrtf(tot * (1.0f/D_MODEL) + 1e-5f);
    const float4 wv = *(const float4*)(w + t*4);
    float4 o = make_float4(v.x*inv*wv.x, v.y*inv*wv.y, v.z*inv*wv.z, v.w*inv*wv.w);
    uint2 hh, ll;
    split4(o, hh, ll);
    ((uint2*)(oh + row*D_MODEL))[t] = hh;
    ((uint2*)(ol + row*D_MODEL))[t] = ll;
}

// ---------------- RoPE (in-place, interleaved pairs) --------------------------
__global__ __launch_bounds__(256) void rope_kernel(float* __restrict__ q)
{
    int idx = blockIdx.x*256 + threadIdx.x;
    int i = idx & 31;
    int h = (idx >> 5) & 15;
    int s = (idx >> 9) & 2047;
    int b = idx >> 20;
    int off = ((b*SEQ + s)*NHEAD + h)*HDIM + 2*i;
    double inv = exp(-(double)i * (9.210340371976184 / 32.0));
    double ang = (double)s * inv;
    float c  = (float)cos(ang);
    float sn = (float)sin(ang);
    float x1 = q[off], x2 = q[off+1];
    q[off]   = x1*c  - x2*sn;
    q[off+1] = x1*sn + x2*c;
}

// ---------------- causal flash attention, fp32, 64x64 tiles ------------------
__global__ __launch_bounds__(256) void attn_kernel(const float* __restrict__ Q,
    const float* __restrict__ Kg, const float* __restrict__ Vg,
    __nv_bfloat16* __restrict__ Oh, __nv_bfloat16* __restrict__ Ol)
{
    __shared__ float Qt[64][64];
    __shared__ float KP[64][64];
    __shared__ float Vs[64][64];
    const int t  = threadIdx.x;
    const int qt = blockIdx.x;
    const int bh = blockIdx.y;
    const int b = bh >> 4, h = bh & 15;
    const int base = (b*SEQ)*D_MODEL + h*HDIM;
    const int lr = t >> 2;

    {
        const float* qp = Q + base + (qt*64 + lr)*D_MODEL;
        #pragma unroll
        for (int j = 0; j < 4; j++) {
            int c = ((t & 3) + j*4)*4;
            float4 v = *(const float4*)(qp + c);
            Qt[c+0][lr] = v.x; Qt[c+1][lr] = v.y; Qt[c+2][lr] = v.z; Qt[c+3][lr] = v.w;
        }
    }
    const int tr = t >> 4, tc = t & 15;
    float m[4], l[4], o[4][4];
    #pragma unroll
    for (int a = 0; a < 4; a++) {
        m[a] = -INFINITY; l[a] = 0.f;
        #pragma unroll
        for (int bb = 0; bb < 4; bb++) o[a][bb] = 0.f;
    }
    __syncthreads();

    for (int kt = 0; kt <= qt; ++kt) {
        {
            const float* kp = Kg + base + (kt*64 + lr)*D_MODEL;
            const float* vp = Vg + base + (kt*64 + lr)*D_MODEL;
            #pragma unroll
            for (int j = 0; j < 4; j++) {
                int c = ((t & 3) + j*4)*4;
                float4 kv = *(const float4*)(kp + c);
                KP[c+0][lr] = kv.x; KP[c+1][lr] = kv.y; KP[c+2][lr] = kv.z; KP[c+3][lr] = kv.w;
                *(float4*)&Vs[lr][c] = *(const float4*)(vp + c);
            }
        }
        __syncthreads();

        float s[4][4];
        #pragma unroll
        for (int a = 0; a < 4; a++)
            #pragma unroll
            for (int bb = 0; bb < 4; bb++) s[a][bb] = 0.f;
        #pragma unroll 8
        for (int d = 0; d < 64; d++) {
            float4 qv = *(const float4*)&Qt[d][tr*4];
            float4 kv = *(const float4*)&KP[d][tc*4];
            float qa[4] = {qv.x,qv.y,qv.z,qv.w};
            float kb[4] = {kv.x,kv.y,kv.z,kv.w};
            #pragma unroll
            for (int a = 0; a < 4; a++)
                #pragma unroll
                for (int bb = 0; bb < 4; bb++) s[a][bb] += qa[a]*kb[bb];
        }

        #pragma unroll
        for (int a = 0; a < 4; a++) {
            int qrow = qt*64 + tr*4 + a;
            float rmax = -INFINITY;
            #pragma unroll
            for (int bb = 0; bb < 4; bb++) {
                int kcol = kt*64 + tc*4 + bb;
                float sv = s[a][bb]*0.125f;
                if (kcol > qrow) sv = -INFINITY;
                s[a][bb] = sv;
                rmax = fmaxf(rmax, sv);
            }
            #pragma unroll
            for (int off = 8; off; off >>= 1)
                rmax = fmaxf(rmax, __shfl_xor_sync(0xffffffffu, rmax, off));
            float mn = fmaxf(m[a], rmax);
            float alpha = expf(m[a] - mn);
            float rsum = 0.f;
            #pragma unroll
            for (int bb = 0; bb < 4; bb++) {
                float p = expf(s[a][bb] - mn);
                s[a][bb] = p;
                rsum += p;
            }
            #pragma unroll
            for (int off = 8; off; off >>= 1)
                rsum += __shfl_xor_sync(0xffffffffu, rsum, off);
            l[a] = l[a]*alpha + rsum;
            m[a] = mn;
            #pragma unroll
            for (int bb = 0; bb < 4; bb++) o[a][bb] *= alpha;
        }
        __syncthreads();

        #pragma unroll
        for (int bb = 0; bb < 4; bb++)
            *(float4*)&KP[tc*4+bb][tr*4] = make_float4(s[0][bb], s[1][bb], s[2][bb], s[3][bb]);
        __syncthreads();

        #pragma unroll 8
        for (int c = 0; c < 64; c++) {
            float4 pv = *(const float4*)&KP[c][tr*4];
            float4 vv = *(const float4*)&Vs[c][tc*4];
            float pa[4] = {pv.x,pv.y,pv.z,pv.w};
            float vb[4] = {vv.x,vv.y,vv.z,vv.w};
            #pragma unroll
            for (int a = 0; a < 4; a++)
                #pragma unroll
                for (int bb = 0; bb < 4; bb++) o[a][bb] += pa[a]*vb[bb];
        }
        __syncthreads();
    }

    #pragma unroll
    for (int a = 0; a < 4; a++) {
        float invl = 1.f/l[a];
        float4 r = make_float4(o[a][0]*invl, o[a][1]*invl, o[a][2]*invl, o[a][3]*invl);
        uint2 hh, ll;
        split4(r, hh, ll);
        size_t off = (size_t)base + (size_t)(qt*64 + tr*4 + a)*D_MODEL + tc*4;
        *(uint2*)(Oh + off) = hh;
        *(uint2*)(Ol + off) = ll;
    }
}

// ---------------- SiLU(g) * u -> split bf16 ----------------------------------
__global__ __launch_bounds__(256) void silu_mul_kernel(const float* __restrict__ g,
        const float* __restrict__ u,
        __nv_bfloat16* __restrict__ hh_, __nv_bfloat16* __restrict__ hl_, int n4)
{
    int i = blockIdx.x*256 + threadIdx.x;
    if (i < n4) {
        float4 gv = ((const float4*)g)[i];
        float4 uv = ((const float4*)u)[i];
        gv.x = gv.x/(1.f+expf(-gv.x))*uv.x;
        gv.y = gv.y/(1.f+expf(-gv.y))*uv.y;
        gv.z = gv.z/(1.f+expf(-gv.z))*uv.z;
        gv.w = gv.w/(1.f+expf(-gv.w))*uv.w;
        uint2 hh, ll;
        split4(gv, hh, ll);
        ((uint2*)hh_)[i] = hh;
        ((uint2*)hl_)[i] = ll;
    }
}

// ---------------- launch -----------------------------------------------------
template <typename T> static T* sym(const void* s) {
    void* p; cudaGetSymbolAddress(&p, s); return (T*)p;
}

extern "C" void kernel_launch(void* const* d_in, const int* in_sizes, int n_in,
                              void* d_out, int out_size)
{
    const float* x   = (const float*)d_in[0];
    const float* wq  = (const float*)d_in[2];
    const float* wk  = (const float*)d_in[3];
    const float* wv  = (const float*)d_in[4];
    const float* wo  = (const float*)d_in[5];
    const float* ln1 = (const float*)d_in[6];
    const float* ln2 = (const float*)d_in[7];
    const float* w1  = (const float*)d_in[8];
    const float* w2  = (const float*)d_in[9];
    const float* w3  = (const float*)d_in[10];
    float* out = (float*)d_out;

    float* qb  = sym<float>(g_q);
    float* kb  = sym<float>(g_k);
    float* vb  = sym<float>(g_v);
    float* x1  = sym<float>(g_x1);
    float* gb  = sym<float>(g_g);
    float* ub  = sym<float>(g_u);
    __nv_bfloat16 *xnh = sym<__nv_bfloat16>(s_xn_h),  *xnl = sym<__nv_bfloat16>(s_xn_l);
    __nv_bfloat16 *ooh = sym<__nv_bfloat16>(s_o_h),   *ool = sym<__nv_bfloat16>(s_o_l);
    __nv_bfloat16 *x2h = sym<__nv_bfloat16>(s_xn2_h), *x2l = sym<__nv_bfloat16>(s_xn2_l);
    __nv_bfloat16 *hh  = sym<__nv_bfloat16>(s_h_h),   *hl  = sym<__nv_bfloat16>(s_h_l);
    __nv_bfloat16 *wqh = sym<__nv_bfloat16>(s_wq_h),  *wql = sym<__nv_bfloat16>(s_wq_l);
    __nv_bfloat16 *wkh = sym<__nv_bfloat16>(s_wk_h),  *wkl = sym<__nv_bfloat16>(s_wk_l);
    __nv_bfloat16 *wvh = sym<__nv_bfloat16>(s_wv_h),  *wvl = sym<__nv_bfloat16>(s_wv_l);
    __nv_bfloat16 *woh = sym<__nv_bfloat16>(s_wo_h),  *wol = sym<__nv_bfloat16>(s_wo_l);
    __nv_bfloat16 *w1h = sym<__nv_bfloat16>(s_w1_h),  *w1l = sym<__nv_bfloat16>(s_w1_l);
    __nv_bfloat16 *w3h = sym<__nv_bfloat16>(s_w3_h),  *w3l = sym<__nv_bfloat16>(s_w3_l);
    __nv_bfloat16 *w2h = sym<__nv_bfloat16>(s_w2_h),  *w2l = sym<__nv_bfloat16>(s_w2_l);

    cudaFuncSetAttribute(hmma_gemm, cudaFuncAttributeMaxDynamicSharedMemorySize, GEMM_SMEM);

    const int nD = D_MODEL*D_MODEL/4, nF = D_FF*D_MODEL/4;
    split_kernel<<<nD/256, 256>>>(wq, wqh, wql, nD);
    split_kernel<<<nD/256, 256>>>(wk, wkh, wkl, nD);
    split_kernel<<<nD/256, 256>>>(wv, wvh, wvl, nD);
    split_kernel<<<nD/256, 256>>>(wo, woh, wol, nD);
    split_kernel<<<nF/256, 256>>>(w1, w1h, w1l, nF);
    split_kernel<<<nF/256, 256>>>(w3, w3h, w3l, nF);
    split_kernel<<<nF/256, 256>>>(w2, w2h, w2l, nF);

    dim3 gD(D_MODEL/128, BS/128);  // (8, 32)
    dim3 gF(D_FF/128,    BS/128);  // (32, 32)

    rmsnorm_kernel<<<BS, 256>>>(x, ln1, xnh, xnl);
    hmma_gemm<<<gD, 256, GEMM_SMEM>>>(xnh, xnl, wqh, wql, nullptr, qb, BS, D_MODEL, D_MODEL);
    hmma_gemm<<<gD, 256, GEMM_SMEM>>>(xnh, xnl, wkh, wkl, nullptr, kb, BS, D_MODEL, D_MODEL);
    hmma_gemm<<<gD, 256, GEMM_SMEM>>>(xnh, xnl, wvh, wvl, nullptr, vb, BS, D_MODEL, D_MODEL);
    rope_kernel<<<(BS*NHEAD*32)/256, 256>>>(qb);
    rope_kernel<<<(BS*NHEAD*32)/256, 256>>>(kb);
    attn_kernel<<<dim3(SEQ/64, BATCH*NHEAD), 256>>>(qb, kb, vb, ooh, ool);
    hmma_gemm<<<gD, 256, GEMM_SMEM>>>(ooh, ool, woh, wol, x, x1, BS, D_MODEL, D_MODEL);
    rmsnorm_kernel<<<BS, 256>>>(x1, ln2, x2h, x2l);
    hmma_gemm<<<gF, 256, GEMM_SMEM>>>(x2h, x2l, w1h, w1l, nullptr, gb, BS, D_FF, D_MODEL);
    hmma_gemm<<<gF, 256, GEMM_SMEM>>>(x2h, x2l, w3h, w3l, nullptr, ub, BS, D_FF, D_MODEL);
    silu_mul_kernel<<<(BS*D_FF/4)/256, 256>>>(gb, ub, hh, hl, BS*D_FF/4);
    hmma_gemm<<<gD, 256, GEMM_SMEM>>>(hh, hl, w2h, w2l, x1, out, BS, D_MODEL, D_FF);
}